// round 8
// baseline (speedup 1.0000x reference)
#include <cuda_runtime.h>
#include <cuda_bf16.h>

#define NPTS  1024
#define CAP   192
#define R2    (0.15f * 0.15f)

__device__ __forceinline__ unsigned long long ffma2(unsigned long long a,
                                                    unsigned long long b,
                                                    unsigned long long c) {
    unsigned long long d;
    asm("fma.rn.f32x2 %0, %1, %2, %3;" : "=l"(d) : "l"(a), "l"(b), "l"(c));
    return d;
}
__device__ __forceinline__ void unpack2(unsigned long long v, float& lo, float& hi) {
    asm("mov.b64 {%0, %1}, %2;" : "=f"(lo), "=f"(hi) : "l"(v));
}

// All 10 nonzero rotation diagonals via the signed-diagonal algebra.
// rot0..3 full-sign (weight 1), rot4..9 single-axis (weight 2).
__device__ __forceinline__ void layer1(float gx, float gy, float gz,
                                       float w1x, float w1y, float w1z,
                                       float b1c, float h[10]) {
    float px = w1x * gx, py = w1y * gy, pz = w1z * gz;
    float a = b1c + px, d = b1c - px;
    float u = py + pz,  v = py - pz;
    h[0] = fmaxf(a + u, 0.f);  h[1] = fmaxf(a - u, 0.f);
    h[2] = fmaxf(d + v, 0.f);  h[3] = fmaxf(d - v, 0.f);
    h[4] = fmaxf(a, 0.f);      h[5] = fmaxf(d, 0.f);
    h[6] = fmaxf(b1c + py, 0.f); h[7] = fmaxf(b1c - py, 0.f);
    h[8] = fmaxf(b1c + pz, 0.f); h[9] = fmaxf(b1c - pz, 0.f);
}

__device__ __forceinline__ void layer2(const float* __restrict__ buf,
                                       const unsigned long long* __restrict__ wpk,
                                       float* __restrict__ mv) {
    #pragma unroll
    for (int r = 0; r < 10; ++r) {
        const ulonglong2* hp = reinterpret_cast<const ulonglong2*>(buf + r * 32);
        unsigned long long acc = 0ull;
        #pragma unroll
        for (int q = 0; q < 8; ++q) {
            ulonglong2 hv = hp[q];               // channels 4q..4q+3
            acc = ffma2(hv.x, wpk[2 * q + 0], acc);
            acc = ffma2(hv.y, wpk[2 * q + 1], acc);
        }
        float lo, hi; unpack2(acc, lo, hi);
        mv[r] = fmaxf(mv[r], lo + hi);
    }
}

__global__ __launch_bounds__(64, 12)
void pe_kernel(const float* __restrict__ x, const float* __restrict__ W1,
               const float* __restrict__ b1, const float* __restrict__ W2,
               const float* __restrict__ b2, float* __restrict__ out)
{
    __shared__ float sg[CAP * 3];                 // in-ball relative coords
    __shared__ float sd2[CAP];
    __shared__ float ssel[63 * 3];                // overflow-selected 63 nearest
    // per-warp 4-deep ring of layer-1 tiles: [warp][buf][rot*32 + channel]
    __shared__ __align__(16) float sh1[2][4][320];
    __shared__ int scnt, sselcnt;

    const int tid  = threadIdx.x;                 // = output channel o (0..63)
    const int wrp  = tid >> 5;
    const int c    = tid & 31;                    // lane = layer-1 channel
    const int b    = blockIdx.x >> 10;
    const int n    = blockIdx.x & (NPTS - 1);
    const float* xb = x + b * NPTS * 3;

    if (tid == 0) { scnt = 0; sselcnt = 0; }
    __syncthreads();

    const float qx = __ldg(&xb[n * 3 + 0]);
    const float qy = __ldg(&xb[n * 3 + 1]);
    const float qz = __ldg(&xb[n * 3 + 2]);

    // ---- ball query: scan points from global (L1/L2 resident, 24 KB) ----
    for (int j = tid; j < NPTS; j += 64) {
        float dx = __ldg(&xb[j * 3 + 0]) - qx;
        float dy = __ldg(&xb[j * 3 + 1]) - qy;
        float dz = __ldg(&xb[j * 3 + 2]) - qz;
        float d2 = dx * dx + dy * dy + dz * dz;
        if (d2 <= R2 && j != n) {
            int p = atomicAdd(&scnt, 1);
            if (p < CAP) {
                sg[p * 3 + 0] = dx; sg[p * 3 + 1] = dy; sg[p * 3 + 2] = dz;
                sd2[p] = d2;
            }
        }
    }
    __syncthreads();

    int cnt = min(scnt, CAP);
    const float* glist = sg;
    int m = cnt;

    // Overflow (>63 others in ball): exact rank-select 63 nearest
    // (top_k parity; statistically unreachable for uniform points).
    if (cnt > 63) {
        for (int e = tid; e < cnt; e += 64) {
            float de = sd2[e];
            int rank = 0;
            for (int f = 0; f < cnt; ++f) {
                float df = sd2[f];
                rank += (df < de) || (df == de && f < e);
            }
            if (rank < 63) {
                int p = atomicAdd(&sselcnt, 1);
                ssel[p * 3 + 0] = sg[e * 3 + 0];
                ssel[p * 3 + 1] = sg[e * 3 + 1];
                ssel[p * 3 + 2] = sg[e * 3 + 2];
            }
        }
        __syncthreads();
        glist = ssel;
        m = 63;
    }

    // ---- per-lane layer-1 weights ----
    const float w1x = __ldg(&W1[c * 3 + 0]);
    const float w1y = __ldg(&W1[c * 3 + 1]);
    const float w1z = __ldg(&W1[c * 3 + 2]);
    const float b1c = __ldg(&b1[c]);

    // ---- W2 row: natural channel-adjacent 64-bit packing ----
    const unsigned long long* w2row =
        reinterpret_cast<const unsigned long long*>(W2 + tid * 32);
    unsigned long long wpk[16];
    const float b2o = __ldg(&b2[tid]);
    float acc_self = 0.f;                 // bias-free response to gp = 0
    #pragma unroll
    for (int q = 0; q < 16; ++q) {
        wpk[q] = __ldg(&w2row[q]);
        float lo, hi; unpack2(wpk[q], lo, hi);
        acc_self = fmaf(lo, fmaxf(__ldg(&b1[2 * q + 0]), 0.f), acc_self);
        acc_self = fmaf(hi, fmaxf(__ldg(&b1[2 * q + 1]), 0.f), acc_self);
    }

    float mv[10];
    #pragma unroll
    for (int r = 0; r < 10; ++r) mv[r] = acc_self;

    float* base = &sh1[wrp][0][0];        // 4 ring buffers of 320 floats

    if (m > 0) {
        float h[10];
        // prologue: fill ring slots 0 and 1 (slot 1 clamps to dup when m==1)
        layer1(glist[0], glist[1], glist[2], w1x, w1y, w1z, b1c, h);
        #pragma unroll
        for (int r = 0; r < 10; ++r) base[r * 32 + c] = h[r];
        {
            int k1 = min(1, m - 1);
            layer1(glist[k1 * 3 + 0], glist[k1 * 3 + 1], glist[k1 * 3 + 2],
                   w1x, w1y, w1z, b1c, h);
            #pragma unroll
            for (int r = 0; r < 10; ++r) base[320 + r * 32 + c] = h[r];
        }
        __syncwarp();

        // depth-2 software pipeline, 2 neighbors per iteration.
        // Odd m / overshoot handled by clamped duplicates (max idempotent).
        for (int k = 0; k < m; k += 2) {
            const int ka = min(k + 2, m - 1);
            const int kb = min(k + 3, m - 1);
            const float gax = glist[ka * 3 + 0], gay = glist[ka * 3 + 1],
                        gaz = glist[ka * 3 + 2];
            const float gbx = glist[kb * 3 + 0], gby = glist[kb * 3 + 1],
                        gbz = glist[kb * 3 + 2];

            float ha[10], hb[10];
            layer1(gax, gay, gaz, w1x, w1y, w1z, b1c, ha);
            layer1(gbx, gby, gbz, w1x, w1y, w1z, b1c, hb);

            // consume slots k, k+1 (stores for them happened >1 iter ago)
            layer2(base + (k & 3) * 320, wpk, mv);
            layer2(base + ((k + 1) & 3) * 320, wpk, mv);

            // produce slots k+2, k+3
            float* bwa = base + ((k + 2) & 3) * 320;
            float* bwb = base + ((k + 3) & 3) * 320;
            #pragma unroll
            for (int r = 0; r < 10; ++r) {
                bwa[r * 32 + c] = ha[r];
                bwb[r * 32 + c] = hb[r];
            }
            __syncwarp();
        }
    }

    // mean over 24 rotations: 4 full (w=1) + 6 axis (w=2) + 8 zero-diag (c2)
    const float c2 = fmaxf(acc_self + b2o, 0.f);
    float fs = 8.f * c2;
    #pragma unroll
    for (int r = 0; r < 4; ++r)  fs += fmaxf(mv[r] + b2o, 0.f);
    #pragma unroll
    for (int r = 4; r < 10; ++r) fs += 2.f * fmaxf(mv[r] + b2o, 0.f);

    out[(b * 64 + tid) * NPTS + n] = fs * (1.f / 24.f);
}

extern "C" void kernel_launch(void* const* d_in, const int* in_sizes, int n_in,
                              void* d_out, int out_size)
{
    const float* x  = (const float*)d_in[0];  // [B,1024,3]
    const float* W1 = (const float*)d_in[1];  // [32,3]
    const float* b1 = (const float*)d_in[2];  // [32]
    const float* W2 = (const float*)d_in[3];  // [64,32]
    const float* b2 = (const float*)d_in[4];  // [64]
    float* out = (float*)d_out;               // [B,64,1024]

    int total_pts = in_sizes[0] / 3;          // B * 1024
    pe_kernel<<<total_pts, 64>>>(x, W1, b1, W2, b2, out);
}

// round 9
// speedup vs baseline: 1.1838x; 1.1838x over previous
#include <cuda_runtime.h>
#include <cuda_bf16.h>

#define NPTS  1024
#define CAP   192
#define R2    (0.15f * 0.15f)

__device__ __forceinline__ unsigned long long ffma2(unsigned long long a,
                                                    unsigned long long b,
                                                    unsigned long long c) {
    unsigned long long d;
    asm("fma.rn.f32x2 %0, %1, %2, %3;" : "=l"(d) : "l"(a), "l"(b), "l"(c));
    return d;
}
__device__ __forceinline__ void unpack2(unsigned long long v, float& lo, float& hi) {
    asm("mov.b64 {%0, %1}, %2;" : "=f"(lo), "=f"(hi) : "l"(v));
}

__global__ __launch_bounds__(64)
void pe_kernel(const float* __restrict__ x, const float* __restrict__ W1,
               const float* __restrict__ b1, const float* __restrict__ W2,
               const float* __restrict__ b2, float* __restrict__ out)
{
    __shared__ float sg[CAP * 3];                 // in-ball relative coords
    __shared__ float sd2[CAP];
    __shared__ float ssel[63 * 3];                // overflow-selected 63 nearest
    // per-warp double-buffered layer-1 tile: [warp][buf][local_rot*32 + ch]
    __shared__ __align__(16) float sh1[2][2][160];
    __shared__ float psum[2][64];                 // per-warp partial rot-sums
    __shared__ int scnt, sselcnt;

    const int tid  = threadIdx.x;
    const int wrp  = tid >> 5;                    // warp0: rots 0-4, warp1: 5-9
    const int c    = tid & 31;                    // lane: layer-1 channel / out row
    const int b    = blockIdx.x >> 10;
    const int n    = blockIdx.x & (NPTS - 1);
    const float* xb = x + b * NPTS * 3;

    if (tid == 0) { scnt = 0; sselcnt = 0; }
    __syncthreads();

    const float qx = __ldg(&xb[n * 3 + 0]);
    const float qy = __ldg(&xb[n * 3 + 1]);
    const float qz = __ldg(&xb[n * 3 + 2]);

    // ---- ball query: scan points from global (L1/L2 resident, 24 KB) ----
    for (int j = tid; j < NPTS; j += 64) {
        float dx = __ldg(&xb[j * 3 + 0]) - qx;
        float dy = __ldg(&xb[j * 3 + 1]) - qy;
        float dz = __ldg(&xb[j * 3 + 2]) - qz;
        float d2 = dx * dx + dy * dy + dz * dz;
        if (d2 <= R2 && j != n) {
            int p = atomicAdd(&scnt, 1);
            if (p < CAP) {
                sg[p * 3 + 0] = dx; sg[p * 3 + 1] = dy; sg[p * 3 + 2] = dz;
                sd2[p] = d2;
            }
        }
    }
    __syncthreads();

    int cnt = min(scnt, CAP);
    const float* glist = sg;
    int m = cnt;

    // Overflow (>63 others in ball): exact rank-select 63 nearest
    // (top_k parity; statistically unreachable for uniform points).
    if (cnt > 63) {
        for (int e = tid; e < cnt; e += 64) {
            float de = sd2[e];
            int rank = 0;
            for (int f = 0; f < cnt; ++f) {
                float df = sd2[f];
                rank += (df < de) || (df == de && f < e);
            }
            if (rank < 63) {
                int p = atomicAdd(&sselcnt, 1);
                ssel[p * 3 + 0] = sg[e * 3 + 0];
                ssel[p * 3 + 1] = sg[e * 3 + 1];
                ssel[p * 3 + 2] = sg[e * 3 + 2];
            }
        }
        __syncthreads();
        glist = ssel;
        m = 63;
    }

    // ---- per-lane layer-1 weights (lane = channel c) ----
    const float w1x = __ldg(&W1[c * 3 + 0]);
    const float w1y = __ldg(&W1[c * 3 + 1]);
    const float w1z = __ldg(&W1[c * 3 + 2]);
    const float b1c = __ldg(&b1[c]);

    // ---- TWO W2 rows per lane: o = c and o = c+32, channel-pair packed ----
    const unsigned long long* w2a =
        reinterpret_cast<const unsigned long long*>(W2 + c * 32);
    const unsigned long long* w2b =
        reinterpret_cast<const unsigned long long*>(W2 + (c + 32) * 32);
    unsigned long long wpa[16], wpb[16];
    const float b2a = __ldg(&b2[c]);
    const float b2b = __ldg(&b2[c + 32]);
    float selfa = 0.f, selfb = 0.f;        // bias-free response to gp = 0
    #pragma unroll
    for (int q = 0; q < 16; ++q) {
        wpa[q] = __ldg(&w2a[q]);
        wpb[q] = __ldg(&w2b[q]);
        float rb0 = fmaxf(__ldg(&b1[2 * q + 0]), 0.f);
        float rb1 = fmaxf(__ldg(&b1[2 * q + 1]), 0.f);
        float la, ha, lb, hb;
        unpack2(wpa[q], la, ha); unpack2(wpb[q], lb, hb);
        selfa = fmaf(la, rb0, fmaf(ha, rb1, selfa));
        selfb = fmaf(lb, rb0, fmaf(hb, rb1, selfb));
    }

    // Running bias-free pre-activation maxes for this warp's 5 rotations.
    float mva[5], mvb[5];
    #pragma unroll
    for (int r = 0; r < 5; ++r) { mva[r] = selfa; mvb[r] = selfb; }

    float* buf0 = &sh1[wrp][0][0];
    float* buf1 = &sh1[wrp][1][0];

    // ---- main loop: double buffer, one __syncwarp per neighbor ----
    for (int k = 0; k < m; ++k) {
        float* buf = (k & 1) ? buf1 : buf0;
        const float gx = glist[k * 3 + 0];
        const float gy = glist[k * 3 + 1];
        const float gz = glist[k * 3 + 2];

        // layer 1: this warp's 5 rotations via signed-diagonal algebra.
        float px = w1x * gx, py = w1y * gy, pz = w1z * gz;
        float h[5];
        if (wrp == 0) {               // full-sign rots 0-3 (w=1) + (+x axis, w=2)
            float a = b1c + px, d = b1c - px;
            float u = py + pz,  v = py - pz;
            h[0] = fmaxf(a + u, 0.f); h[1] = fmaxf(a - u, 0.f);
            h[2] = fmaxf(d + v, 0.f); h[3] = fmaxf(d - v, 0.f);
            h[4] = fmaxf(a, 0.f);
        } else {                      // (-x, +y, -y, +z, -z) axes, w=2 each
            h[0] = fmaxf(b1c - px, 0.f);
            h[1] = fmaxf(b1c + py, 0.f); h[2] = fmaxf(b1c - py, 0.f);
            h[3] = fmaxf(b1c + pz, 0.f); h[4] = fmaxf(b1c - pz, 0.f);
        }
        #pragma unroll
        for (int r = 0; r < 5; ++r) buf[r * 32 + c] = h[r];
        __syncwarp();

        // layer 2: each h load feeds BOTH W2 rows -> 1 LDS.128 : 4 FFMA2.
        #pragma unroll
        for (int r = 0; r < 5; ++r) {
            const ulonglong2* hp =
                reinterpret_cast<const ulonglong2*>(buf + r * 32);
            unsigned long long aa = 0ull, ab = 0ull;
            #pragma unroll
            for (int q = 0; q < 8; ++q) {
                ulonglong2 hv = hp[q];           // channels 4q..4q+3
                aa = ffma2(hv.x, wpa[2 * q + 0], aa);
                ab = ffma2(hv.x, wpb[2 * q + 0], ab);
                aa = ffma2(hv.y, wpa[2 * q + 1], aa);
                ab = ffma2(hv.y, wpb[2 * q + 1], ab);
            }
            float lo, hi;
            unpack2(aa, lo, hi); mva[r] = fmaxf(mva[r], lo + hi);
            unpack2(ab, lo, hi); mvb[r] = fmaxf(mvb[r], lo + hi);
        }
    }

    // ---- per-warp weighted rot-sums, then cross-warp combine ----
    float pa = 0.f, pb = 0.f;
    #pragma unroll
    for (int r = 0; r < 5; ++r) {
        float wr = (wrp == 0 && r < 4) ? 1.f : 2.f;
        pa += wr * fmaxf(mva[r] + b2a, 0.f);
        pb += wr * fmaxf(mvb[r] + b2b, 0.f);
    }
    psum[wrp][c]      = pa;
    psum[wrp][c + 32] = pb;
    __syncthreads();

    // 8 zero-diagonal rotations contribute the constant c2 (own channel):
    // thread tid<32 owns row c=tid (selfa/b2a); tid>=32 owns row tid (selfb/b2b).
    const float c2 = (tid < 32) ? fmaxf(selfa + b2a, 0.f)
                                : fmaxf(selfb + b2b, 0.f);
    float fs = psum[0][tid] + psum[1][tid] + 8.f * c2;
    out[(b * 64 + tid) * NPTS + n] = fs * (1.f / 24.f);
}

extern "C" void kernel_launch(void* const* d_in, const int* in_sizes, int n_in,
                              void* d_out, int out_size)
{
    const float* x  = (const float*)d_in[0];  // [B,1024,3]
    const float* W1 = (const float*)d_in[1];  // [32,3]
    const float* b1 = (const float*)d_in[2];  // [32]
    const float* W2 = (const float*)d_in[3];  // [64,32]
    const float* b2 = (const float*)d_in[4];  // [64]
    float* out = (float*)d_out;               // [B,64,1024]

    int total_pts = in_sizes[0] / 3;          // B * 1024
    pe_kernel<<<total_pts, 64>>>(x, W1, b1, W2, b2, out);
}